// round 15
// baseline (speedup 1.0000x reference)
#include <cuda_runtime.h>
#include <cuda_bf16.h>
#include <string.h>
#include <stdint.h>

#define DIM   100
#define KBS   4950
#define NN    (DIM * DIM)
#define MAXB  2048

#define NT 13      // n8 tiles  (104 = pad of 100)
#define KT 7       // k16 tiles (112 = pad of 100)

// ---- device scratch (no runtime allocation) ----
__device__ float2  g_U[NN];
__device__ float4  g_rot[KBS];
__device__ float2  g_dph[DIM];
// A1 frags: [mat(3: Ur,Ui,Ur+Ui)][split(2)][mtile(8)][ktile(7)][lane(32)][reg(4)]
__device__ uint32_t g_A1[3 * 2 * 8 * KT * 32 * 4];
// B2 frags: [mat(2)][split(2)][ktile(7)][ntile(13)][lane(32)][reg(2)]
__device__ uint32_t g_B2[2 * 2 * KT * NT * 32 * 2];

// ---------------- helpers ----------------
__device__ __forceinline__ void hl_split(float v0, float v1,
                                         uint32_t& h, uint32_t& l) {
    const __nv_bfloat16 h0 = __float2bfloat16(v0);
    const __nv_bfloat16 h1 = __float2bfloat16(v1);
    h = (uint32_t)__bfloat16_as_ushort(h0)
      | ((uint32_t)__bfloat16_as_ushort(h1) << 16);
    const __nv_bfloat16 l0 = __float2bfloat16(v0 - __bfloat162float(h0));
    const __nv_bfloat16 l1 = __float2bfloat16(v1 - __bfloat162float(h1));
    l = (uint32_t)__bfloat16_as_ushort(l0)
      | ((uint32_t)__bfloat16_as_ushort(l1) << 16);
}
__device__ __forceinline__ void mma16816(float* d, const uint32_t* a,
                                         uint32_t b0, uint32_t b1) {
    asm volatile(
        "mma.sync.aligned.m16n8k16.row.col.f32.bf16.bf16.f32 "
        "{%0,%1,%2,%3}, {%4,%5,%6,%7}, {%8,%9}, {%0,%1,%2,%3};"
        : "+f"(d[0]), "+f"(d[1]), "+f"(d[2]), "+f"(d[3])
        : "r"(a[0]), "r"(a[1]), "r"(a[2]), "r"(a[3]), "r"(b0), "r"(b1));
}

// ---------------------------------------------------------------------------
// Kernel 0: rotation coefficients.
// ---------------------------------------------------------------------------
__global__ void rot_prep(const float* __restrict__ theta,
                         const float* __restrict__ phi,
                         const float* __restrict__ diag) {
    const int i = blockIdx.x * blockDim.x + threadIdx.x;
    if (i < KBS) {
        float st, ct, sp, cp;
        sincosf(theta[i], &st, &ct);
        sincosf(phi[i],   &sp, &cp);
        g_rot[i] = make_float4(ct, st, cp, sp);
    }
    if (i < DIM) {
        float sd, cd;
        sincosf(diag[i], &sd, &cd);
        g_dph[i] = make_float2(cd, sd);
    }
}

// ---------------------------------------------------------------------------
// Kernel 1: build U (one CTA per column, prefetched serial scan).
// ---------------------------------------------------------------------------
__global__ void build_U() {
    __shared__ float2 col[DIM];
    const int c   = blockIdx.x;
    const int tid = threadIdx.x;          // 64 threads

    for (int r = tid; r < DIM; r += 64)
        col[r] = make_float2(r == c ? 1.0f : 0.0f, 0.0f);
    __syncthreads();

    float4 rc_next = make_float4(1.f, 0.f, 1.f, 0.f);
    if (tid < 50) rc_next = g_rot[tid];

    int off = 0;
    for (int layer = 0; layer < DIM; ++layer) {
        const int start = layer & 1;
        const int np    = (DIM - start) >> 1;
        const float4 rc = rc_next;
        const int noff  = off + np;
        if (layer + 1 < DIM) {
            const int nnp = (DIM - ((layer + 1) & 1)) >> 1;
            if (tid < nnp) rc_next = g_rot[noff + tid];
        }
        if (tid < np) {
            const int m = start + 2 * tid;
            const float2 rm = col[m];
            const float2 rn = col[m + 1];
            const float er = rc.z * rm.x - rc.w * rm.y;
            const float ei = rc.z * rm.y + rc.w * rm.x;
            col[m]     = make_float2(rc.x * er - rc.y * rn.x,
                                     rc.x * ei - rc.y * rn.y);
            col[m + 1] = make_float2(rc.y * er + rc.x * rn.x,
                                     rc.y * ei + rc.x * rn.y);
        }
        off = noff;
        __syncthreads();
    }
    for (int r = tid; r < DIM; r += 64) {
        const float2 d = g_dph[r];
        const float2 v = col[r];
        g_U[r * DIM + c] = make_float2(d.x * v.x - d.y * v.y,
                                       d.x * v.y + d.y * v.x);
    }
}

// U element (mat 0 = Ur, 1 = Ui, 2 = Ur+Ui), zero-padded outside 100x100
__device__ __forceinline__ float u_el(int mat, int r, int k) {
    if (r >= DIM || k >= DIM) return 0.0f;
    const float2 u = g_U[r * DIM + k];
    return mat == 0 ? u.x : (mat == 1 ? u.y : u.x + u.y);
}

// ---------------------------------------------------------------------------
// Kernel 2: precompute batch-invariant mma fragments.
// ---------------------------------------------------------------------------
__global__ void frag_prep() {
    const int i0 = blockIdx.x * blockDim.x + threadIdx.x;
    const int stride = gridDim.x * blockDim.x;

    const int NA = 3 * 2 * 8 * KT * 32 * 4;
    for (int e = i0; e < NA; e += stride) {
        int t = e;
        const int reg = t & 3;  t >>= 2;
        const int lane = t & 31; t >>= 5;
        const int kt = t % KT;   t /= KT;
        const int mt = t & 7;    t >>= 3;
        const int split = t & 1; t >>= 1;
        const int mat = t;       // 0..2
        const int row = mt * 16 + (lane >> 2) + 8 * (reg & 1);
        const int col = kt * 16 + (lane & 3) * 2 + 8 * (reg >> 1);
        const float v0 = u_el(mat, row, col);
        const float v1 = u_el(mat, row, col + 1);
        uint32_t h, l;
        hl_split(v0, v1, h, l);
        g_A1[e] = split == 0 ? h : l;
    }

    const int NB = 2 * 2 * KT * NT * 32 * 2;
    for (int e = i0; e < NB; e += stride) {
        int t = e;
        const int reg = t & 1;   t >>= 1;
        const int lane = t & 31; t >>= 5;
        const int nt = t % NT;   t /= NT;
        const int kt = t % KT;   t /= KT;
        const int split = t & 1; t >>= 1;
        const int mat = t;
        const int k = kt * 16 + (lane & 3) * 2 + 8 * reg;
        const int n = nt * 8 + (lane >> 2);
        // B[k][n] = U^T[k][n] = U[n][k]
        const float v0 = u_el(mat, n, k);
        const float v1 = u_el(mat, n, k + 1);
        uint32_t h, l;
        hl_split(v0, v1, h, l);
        g_B2[e] = split == 0 ? h : l;
    }
}

// ---------------------------------------------------------------------------
// Kernel 3: fused per-batch HMMA transform, Karatsuba stage 1.
//   m1 = Ur Xr ; m2 = Ui Xi ; m3 = (Ur+Ui)(Xr+Xi)
//   P = m1 - m2 ; Q = m3 - m1 - m2
//   Re(O) = P Ur^T + Q Ui^T
// 256 threads = 8 warps; warp w owns output rows 16w..16w+15.
// ---------------------------------------------------------------------------
__global__ void __launch_bounds__(256)
fused_mma(const float* __restrict__ xre, const float* __restrict__ xim,
          float* __restrict__ outf, int out_floats) {
    // transposed, pre-split X chunk: [q(104)][j(8 pair-words)], stride 12
    __shared__ uint32_t XrH[104 * 12], XrL[104 * 12];
    __shared__ uint32_t XiH[104 * 12], XiL[104 * 12];
    __shared__ uint32_t XsH[104 * 12], XsL[104 * 12];   // Xr+Xi splits

    const int tid  = threadIdx.x;
    const int warp = tid >> 5;
    const int lane = tid & 31;
    const int nl   = lane >> 2;       // 0..7
    const int mm   = lane & 3;        // 0..3
    const int base = blockIdx.x * NN;

    float M1[NT][4], M2[NT][4], M3[NT][4];
    #pragma unroll
    for (int n = 0; n < NT; ++n)
        #pragma unroll
        for (int r = 0; r < 4; ++r) { M1[n][r] = 0.f; M2[n][r] = 0.f; M3[n][r] = 0.f; }

    // -------- stage 1: k-chunk loop --------
    for (int c = 0; c < KT; ++c) {
        __syncthreads();
        for (int e = tid; e < 8 * 104; e += 256) {
            const int j = e / 104;          // 0..7
            const int q = e - j * 104;      // 0..103
            const int p = 16 * c + 2 * j;
            float r0 = 0.f, r1 = 0.f, i0v = 0.f, i1v = 0.f;
            if (q < DIM) {
                if (p < DIM)     { r0 = xre[base + p * DIM + q];
                                   i0v = xim[base + p * DIM + q]; }
                if (p + 1 < DIM) { r1 = xre[base + (p + 1) * DIM + q];
                                   i1v = xim[base + (p + 1) * DIM + q]; }
            }
            uint32_t h, l;
            hl_split(r0, r1, h, l);
            XrH[q * 12 + j] = h; XrL[q * 12 + j] = l;
            hl_split(i0v, i1v, h, l);
            XiH[q * 12 + j] = h; XiL[q * 12 + j] = l;
            hl_split(r0 + i0v, r1 + i1v, h, l);
            XsH[q * 12 + j] = h; XsL[q * 12 + j] = l;
        }
        __syncthreads();

        // A fragments: Ur, Ui, Ur+Ui (hi+lo each)
        uint32_t ArH[4], ArL[4], AiH[4], AiL[4], AsH[4], AsL[4];
        {
            const int bA = ((warp * KT + c) * 32 + lane) * 4;
            const int mstr = 2 * 8 * KT * 32 * 4;   // mat stride
            const int sstr = 8 * KT * 32 * 4;       // split stride
            *(uint4*)ArH = *(const uint4*)&g_A1[bA];
            *(uint4*)ArL = *(const uint4*)&g_A1[bA + sstr];
            *(uint4*)AiH = *(const uint4*)&g_A1[bA + mstr];
            *(uint4*)AiL = *(const uint4*)&g_A1[bA + mstr + sstr];
            *(uint4*)AsH = *(const uint4*)&g_A1[bA + 2 * mstr];
            *(uint4*)AsL = *(const uint4*)&g_A1[bA + 2 * mstr + sstr];
        }

        #pragma unroll
        for (int n = 0; n < NT; ++n) {
            const int qb = (8 * n + nl) * 12;
            const uint32_t xrh0 = XrH[qb + mm], xrh1 = XrH[qb + 4 + mm];
            const uint32_t xrl0 = XrL[qb + mm], xrl1 = XrL[qb + 4 + mm];
            const uint32_t xih0 = XiH[qb + mm], xih1 = XiH[qb + 4 + mm];
            const uint32_t xil0 = XiL[qb + mm], xil1 = XiL[qb + 4 + mm];
            const uint32_t xsh0 = XsH[qb + mm], xsh1 = XsH[qb + 4 + mm];
            const uint32_t xsl0 = XsL[qb + mm], xsl1 = XsL[qb + 4 + mm];
            // m1 += Ur*Xr
            mma16816(M1[n], ArH, xrh0, xrh1);
            mma16816(M1[n], ArH, xrl0, xrl1);
            mma16816(M1[n], ArL, xrh0, xrh1);
            // m2 += Ui*Xi
            mma16816(M2[n], AiH, xih0, xih1);
            mma16816(M2[n], AiH, xil0, xil1);
            mma16816(M2[n], AiL, xih0, xih1);
            // m3 += (Ur+Ui)*(Xr+Xi)
            mma16816(M3[n], AsH, xsh0, xsh1);
            mma16816(M3[n], AsH, xsl0, xsl1);
            mma16816(M3[n], AsL, xsh0, xsh1);
        }
    }

    // Karatsuba combine: P -> M1, Q -> M2 (M3 freed for O)
    #pragma unroll
    for (int n = 0; n < NT; ++n)
        #pragma unroll
        for (int r = 0; r < 4; ++r) {
            const float m1 = M1[n][r], m2 = M2[n][r], m3 = M3[n][r];
            M1[n][r] = m1 - m2;             // P
            M2[n][r] = m3 - m1 - m2;        // Q
            M3[n][r] = 0.f;                 // O accumulator
        }

    // -------- stage 2: O = P Ur^T + Q Ui^T --------
    const int mstrB = 2 * KT * NT * 32 * 2;
    const int sstrB = KT * NT * 32 * 2;

    #pragma unroll
    for (int t = 0; t < KT; ++t) {
        uint32_t PAH[4], PAL[4], QAH[4], QAL[4];
        hl_split(M1[2 * t][0], M1[2 * t][1], PAH[0], PAL[0]);
        hl_split(M1[2 * t][2], M1[2 * t][3], PAH[1], PAL[1]);
        hl_split(M2[2 * t][0], M2[2 * t][1], QAH[0], QAL[0]);
        hl_split(M2[2 * t][2], M2[2 * t][3], QAH[1], QAL[1]);
        if (t < 6) {
            hl_split(M1[2 * t + 1][0], M1[2 * t + 1][1], PAH[2], PAL[2]);
            hl_split(M1[2 * t + 1][2], M1[2 * t + 1][3], PAH[3], PAL[3]);
            hl_split(M2[2 * t + 1][0], M2[2 * t + 1][1], QAH[2], QAL[2]);
            hl_split(M2[2 * t + 1][2], M2[2 * t + 1][3], QAH[3], QAL[3]);
        } else {
            PAH[2] = PAH[3] = PAL[2] = PAL[3] = 0u;
            QAH[2] = QAH[3] = QAL[2] = QAL[3] = 0u;
        }

        #pragma unroll
        for (int n = 0; n < NT; ++n) {
            const int bB = ((t * NT + n) * 32 + lane) * 2;
            uint2 brh = *(const uint2*)&g_B2[bB];                   // Ur hi
            uint2 brl = *(const uint2*)&g_B2[bB + sstrB];           // Ur lo
            uint2 bih = *(const uint2*)&g_B2[bB + mstrB];           // Ui hi
            uint2 bil = *(const uint2*)&g_B2[bB + mstrB + sstrB];   // Ui lo
            mma16816(M3[n], PAH, brh.x, brh.y);
            mma16816(M3[n], PAH, brl.x, brl.y);
            mma16816(M3[n], PAL, brh.x, brh.y);
            mma16816(M3[n], QAH, bih.x, bih.y);
            mma16816(M3[n], QAH, bil.x, bil.y);
            mma16816(M3[n], QAL, bih.x, bih.y);
        }
    }

    // -------- store --------
    const int r0 = warp * 16 + nl;
    #pragma unroll
    for (int n = 0; n < NT; ++n) {
        const int c0 = n * 8 + 2 * mm;
        if (c0 + 1 >= DIM) continue;
        if (r0 < DIM) {
            const int idx = base + r0 * DIM + c0;
            if (idx + 2 <= out_floats)
                *(float2*)&outf[idx] = make_float2(M3[n][0], M3[n][1]);
        }
        if (r0 + 8 < DIM) {
            const int idx = base + (r0 + 8) * DIM + c0;
            if (idx + 2 <= out_floats)
                *(float2*)&outf[idx] = make_float2(M3[n][2], M3[n][3]);
        }
    }
}

// Diagnostic fallback
__global__ void diag_mark_kernel(float* out) { out[0] = 0.0f; }

extern "C" void kernel_launch(void* const* d_in, const int* in_sizes, int n_in,
                              void* d_out, int out_size) {
    int smin = 0x7fffffff;
    for (int i = 0; i < n_in; ++i)
        if (in_sizes[i] < smin) smin = in_sizes[i];

    int unit = 0;
    if (smin == DIM)          unit = 1;
    else if (smin == DIM * 4) unit = 4;

    const float* xre = nullptr; const float* xim = nullptr;
    const float* theta = nullptr; const float* phi = nullptr;
    const float* diag = nullptr;
    int nbatch = 0, big = 0;
    bool ok = (unit != 0) && (n_in == 5);

    if (ok) {
        int norm[8];
        int diag_slot = -1;
        for (int i = 0; i < n_in; ++i) {
            norm[i] = in_sizes[i] / unit;
            if (norm[i] == DIM) diag_slot = i;
            if (norm[i] > big) big = norm[i];
        }
        if (diag_slot == 0 && norm[1] == KBS && norm[2] == KBS) {
            diag  = (const float*)d_in[0];
            phi   = (const float*)d_in[1];
            theta = (const float*)d_in[2];
            xre   = (const float*)d_in[3];
            xim   = (const float*)d_in[4];
        } else {
            for (int i = 0; i < n_in; ++i) {
                const float* p = (const float*)d_in[i];
                if (norm[i] == KBS)      { if (!theta) theta = p; else phi = p; }
                else if (norm[i] == DIM) { diag = p; }
                else if (norm[i] == big) { if (!xre) xre = p; else xim = p; }
            }
        }
        nbatch = big / NN;
        ok = xre && xim && theta && phi && diag &&
             nbatch > 0 && nbatch <= MAXB && (big == nbatch * NN);
    }

    if (!ok) {
        diag_mark_kernel<<<1, 1>>>((float*)d_out);
        return;
    }

    const int want = nbatch * NN;
    const int out_floats = (out_size < want) ? out_size : want;

    rot_prep<<<(KBS + 127) / 128, 128>>>(theta, phi, diag);
    build_U<<<DIM, 64>>>();
    frag_prep<<<128, 256>>>();
    fused_mma<<<nbatch, 256>>>(xre, xim, (float*)d_out, out_floats);
}

// round 16
// speedup vs baseline: 1.1270x; 1.1270x over previous
#include <cuda_runtime.h>
#include <cuda_bf16.h>
#include <string.h>
#include <stdint.h>

#define DIM   100
#define KBS   4950
#define NN    (DIM * DIM)
#define MAXB  2048

#define NT 13      // n8 tiles  (104 = pad of 100)
#define KT 7       // k16 tiles (112 = pad of 100)

// dynamic smem: 4 planes (Ph,Pl,Qh,Ql) of 128 rows x 52 pair-words
#define PLANE     (128 * 52)
#define SMEM_DYN  (4 * PLANE * 4)     // 106496 B

// ---- device scratch (no runtime allocation) ----
__device__ float2  g_U[NN];
__device__ float4  g_rot[KBS];
__device__ float2  g_dph[DIM];
// A1 frags: [mat(2: Ur,Ui)][split(2)][mtile(8)][ktile(7)][lane(32)][reg(4)]
__device__ uint32_t g_A1[2 * 2 * 8 * KT * 32 * 4];
// B2 frags: [mat(2)][split(2)][ktile(7)][ntile(13)][lane(32)][reg(2)]
__device__ uint32_t g_B2[2 * 2 * KT * NT * 32 * 2];

// ---------------- helpers ----------------
__device__ __forceinline__ void hl_split(float v0, float v1,
                                         uint32_t& h, uint32_t& l) {
    const __nv_bfloat16 h0 = __float2bfloat16(v0);
    const __nv_bfloat16 h1 = __float2bfloat16(v1);
    h = (uint32_t)__bfloat16_as_ushort(h0)
      | ((uint32_t)__bfloat16_as_ushort(h1) << 16);
    const __nv_bfloat16 l0 = __float2bfloat16(v0 - __bfloat162float(h0));
    const __nv_bfloat16 l1 = __float2bfloat16(v1 - __bfloat162float(h1));
    l = (uint32_t)__bfloat16_as_ushort(l0)
      | ((uint32_t)__bfloat16_as_ushort(l1) << 16);
}
__device__ __forceinline__ void mma16816(float* d, const uint32_t* a,
                                         uint32_t b0, uint32_t b1) {
    asm volatile(
        "mma.sync.aligned.m16n8k16.row.col.f32.bf16.bf16.f32 "
        "{%0,%1,%2,%3}, {%4,%5,%6,%7}, {%8,%9}, {%0,%1,%2,%3};"
        : "+f"(d[0]), "+f"(d[1]), "+f"(d[2]), "+f"(d[3])
        : "r"(a[0]), "r"(a[1]), "r"(a[2]), "r"(a[3]), "r"(b0), "r"(b1));
}

// ---------------------------------------------------------------------------
// Kernel 0: rotation coefficients.
// ---------------------------------------------------------------------------
__global__ void rot_prep(const float* __restrict__ theta,
                         const float* __restrict__ phi,
                         const float* __restrict__ diag) {
    const int i = blockIdx.x * blockDim.x + threadIdx.x;
    if (i < KBS) {
        float st, ct, sp, cp;
        sincosf(theta[i], &st, &ct);
        sincosf(phi[i],   &sp, &cp);
        g_rot[i] = make_float4(ct, st, cp, sp);
    }
    if (i < DIM) {
        float sd, cd;
        sincosf(diag[i], &sd, &cd);
        g_dph[i] = make_float2(cd, sd);
    }
}

// ---------------------------------------------------------------------------
// Kernel 1: build U (one CTA per column, prefetched serial scan).
// ---------------------------------------------------------------------------
__global__ void build_U() {
    __shared__ float2 col[DIM];
    const int c   = blockIdx.x;
    const int tid = threadIdx.x;          // 64 threads

    for (int r = tid; r < DIM; r += 64)
        col[r] = make_float2(r == c ? 1.0f : 0.0f, 0.0f);
    __syncthreads();

    float4 rc_next = make_float4(1.f, 0.f, 1.f, 0.f);
    if (tid < 50) rc_next = g_rot[tid];

    int off = 0;
    for (int layer = 0; layer < DIM; ++layer) {
        const int start = layer & 1;
        const int np    = (DIM - start) >> 1;
        const float4 rc = rc_next;
        const int noff  = off + np;
        if (layer + 1 < DIM) {
            const int nnp = (DIM - ((layer + 1) & 1)) >> 1;
            if (tid < nnp) rc_next = g_rot[noff + tid];
        }
        if (tid < np) {
            const int m = start + 2 * tid;
            const float2 rm = col[m];
            const float2 rn = col[m + 1];
            const float er = rc.z * rm.x - rc.w * rm.y;
            const float ei = rc.z * rm.y + rc.w * rm.x;
            col[m]     = make_float2(rc.x * er - rc.y * rn.x,
                                     rc.x * ei - rc.y * rn.y);
            col[m + 1] = make_float2(rc.y * er + rc.x * rn.x,
                                     rc.y * ei + rc.x * rn.y);
        }
        off = noff;
        __syncthreads();
    }
    for (int r = tid; r < DIM; r += 64) {
        const float2 d = g_dph[r];
        const float2 v = col[r];
        g_U[r * DIM + c] = make_float2(d.x * v.x - d.y * v.y,
                                       d.x * v.y + d.y * v.x);
    }
}

// U element (mat 0 = Ur, 1 = Ui), zero-padded outside 100x100
__device__ __forceinline__ float u_el(int mat, int r, int k) {
    if (r >= DIM || k >= DIM) return 0.0f;
    const float2 u = g_U[r * DIM + k];
    return mat == 0 ? u.x : u.y;
}

// ---------------------------------------------------------------------------
// Kernel 2: precompute batch-invariant mma fragments of Ur/Ui.
// ---------------------------------------------------------------------------
__global__ void frag_prep() {
    const int i0 = blockIdx.x * blockDim.x + threadIdx.x;
    const int stride = gridDim.x * blockDim.x;

    const int NA = 2 * 2 * 8 * KT * 32 * 4;
    for (int e = i0; e < NA; e += stride) {
        int t = e;
        const int reg = t & 3;  t >>= 2;
        const int lane = t & 31; t >>= 5;
        const int kt = t % KT;   t /= KT;
        const int mt = t & 7;    t >>= 3;
        const int split = t & 1; t >>= 1;
        const int mat = t;
        const int row = mt * 16 + (lane >> 2) + 8 * (reg & 1);
        const int col = kt * 16 + (lane & 3) * 2 + 8 * (reg >> 1);
        const float v0 = u_el(mat, row, col);
        const float v1 = u_el(mat, row, col + 1);
        uint32_t h, l;
        hl_split(v0, v1, h, l);
        g_A1[e] = split == 0 ? h : l;
    }

    const int NB = 2 * 2 * KT * NT * 32 * 2;
    for (int e = i0; e < NB; e += stride) {
        int t = e;
        const int reg = t & 1;   t >>= 1;
        const int lane = t & 31; t >>= 5;
        const int nt = t % NT;   t /= NT;
        const int kt = t % KT;   t /= KT;
        const int split = t & 1; t >>= 1;
        const int mat = t;
        const int k = kt * 16 + (lane & 3) * 2 + 8 * reg;
        const int n = nt * 8 + (lane >> 2);
        // B[k][n] = U^T[k][n] = U[n][k]
        const float v0 = u_el(mat, n, k);
        const float v1 = u_el(mat, n, k + 1);
        uint32_t h, l;
        hl_split(v0, v1, h, l);
        g_B2[e] = split == 0 ? h : l;
    }
}

// ---------------------------------------------------------------------------
// Kernel 3: fused per-batch HMMA transform, 16 warps.
//   warp = (wm = m-tile 0..7, wh = n-half 0..1)
//   stage 1: P = Ur Xr - Ui Xi ; Q = Ur Xi + Ui Xr   (warp's n-half only)
//   P,Q -> smem as bf16 split pair-words (overlaying dead X buffers)
//   stage 2: Re(O) = P Ur^T + Q Ui^T  (full k from smem; warp's n-half out)
// ---------------------------------------------------------------------------
__global__ void __launch_bounds__(512)
fused_mma(const float* __restrict__ xre, const float* __restrict__ xim,
          float* __restrict__ outf, int out_floats) {
    extern __shared__ uint32_t sh[];
    // stage-2 planes (after stage 1): [row(128)][kpair(52)]
    uint32_t* sPh = sh;
    uint32_t* sPl = sh + PLANE;
    uint32_t* sQh = sh + 2 * PLANE;
    uint32_t* sQl = sh + 3 * PLANE;
    // stage-1 X overlay (dead before P/Q written): 6 planes of 104*12
    uint32_t* XrH = sh;              uint32_t* XrL = sh + 1248;
    uint32_t* XiH = sh + 2 * 1248;   uint32_t* XiL = sh + 3 * 1248;

    const int tid  = threadIdx.x;
    const int warp = tid >> 5;
    const int lane = tid & 31;
    const int wm   = warp & 7;        // m-tile
    const int wh   = warp >> 3;       // n-half
    const int nl   = lane >> 2;       // 0..7
    const int mm   = lane & 3;        // 0..3
    const int base = blockIdx.x * NN;

    const int nbase = wh * 7;                 // first n-tile of this half
    const int ncnt  = wh ? 6 : 7;             // tiles in this half

    float P[7][4], Q[7][4];
    #pragma unroll
    for (int n = 0; n < 7; ++n)
        #pragma unroll
        for (int r = 0; r < 4; ++r) { P[n][r] = 0.f; Q[n][r] = 0.f; }

    // -------- stage 1: k-chunk loop --------
    for (int c = 0; c < KT; ++c) {
        __syncthreads();
        for (int e = tid; e < 8 * 104; e += 512) {
            const int j = e / 104;          // 0..7
            const int q = e - j * 104;      // 0..103
            const int p = 16 * c + 2 * j;
            float r0 = 0.f, r1 = 0.f, i0v = 0.f, i1v = 0.f;
            if (q < DIM) {
                if (p < DIM)     { r0 = xre[base + p * DIM + q];
                                   i0v = xim[base + p * DIM + q]; }
                if (p + 1 < DIM) { r1 = xre[base + (p + 1) * DIM + q];
                                   i1v = xim[base + (p + 1) * DIM + q]; }
            }
            uint32_t h, l;
            hl_split(r0, r1, h, l);
            XrH[q * 12 + j] = h; XrL[q * 12 + j] = l;
            hl_split(i0v, i1v, h, l);
            XiH[q * 12 + j] = h; XiL[q * 12 + j] = l;
        }
        __syncthreads();

        uint32_t WrHf[4], WrLf[4], WiHf[4], WiLf[4];
        {
            const int bA = ((wm * KT + c) * 32 + lane) * 4;
            const int mstr = 2 * 8 * KT * 32 * 4;
            const int sstr = 8 * KT * 32 * 4;
            *(uint4*)WrHf = *(const uint4*)&g_A1[bA];
            *(uint4*)WrLf = *(const uint4*)&g_A1[bA + sstr];
            *(uint4*)WiHf = *(const uint4*)&g_A1[bA + mstr];
            *(uint4*)WiLf = *(const uint4*)&g_A1[bA + mstr + sstr];
        }

        #pragma unroll
        for (int ln = 0; ln < 7; ++ln) {
            if (ln >= ncnt) break;
            const int n  = nbase + ln;
            const int qb = (8 * n + nl) * 12;
            const uint32_t xrh0 = XrH[qb + mm], xrh1 = XrH[qb + 4 + mm];
            const uint32_t xrl0 = XrL[qb + mm], xrl1 = XrL[qb + 4 + mm];
            const uint32_t xih0 = XiH[qb + mm], xih1 = XiH[qb + 4 + mm];
            const uint32_t xil0 = XiL[qb + mm], xil1 = XiL[qb + 4 + mm];
            const uint32_t nih0 = xih0 ^ 0x80008000u, nih1 = xih1 ^ 0x80008000u;
            const uint32_t nil0 = xil0 ^ 0x80008000u, nil1 = xil1 ^ 0x80008000u;
            // P += Ur*Xr - Ui*Xi
            mma16816(P[ln], WrHf, xrh0, xrh1);
            mma16816(P[ln], WrHf, xrl0, xrl1);
            mma16816(P[ln], WrLf, xrh0, xrh1);
            mma16816(P[ln], WiHf, nih0, nih1);
            mma16816(P[ln], WiHf, nil0, nil1);
            mma16816(P[ln], WiLf, nih0, nih1);
            // Q += Ur*Xi + Ui*Xr
            mma16816(Q[ln], WrHf, xih0, xih1);
            mma16816(Q[ln], WrHf, xil0, xil1);
            mma16816(Q[ln], WrLf, xih0, xih1);
            mma16816(Q[ln], WiHf, xrh0, xrh1);
            mma16816(Q[ln], WiHf, xrl0, xrl1);
            mma16816(Q[ln], WiLf, xrh0, xrh1);
        }
    }

    // -------- P,Q -> smem pair-word planes (X overlay now dead) --------
    __syncthreads();
    {
        const int row0 = wm * 16 + nl;
        #pragma unroll
        for (int ln = 0; ln < 7; ++ln) {
            if (ln >= ncnt) break;
            const int kp = 4 * (nbase + ln) + mm;
            uint32_t h, l;
            hl_split(P[ln][0], P[ln][1], h, l);
            sPh[row0 * 52 + kp] = h; sPl[row0 * 52 + kp] = l;
            hl_split(P[ln][2], P[ln][3], h, l);
            sPh[(row0 + 8) * 52 + kp] = h; sPl[(row0 + 8) * 52 + kp] = l;
            hl_split(Q[ln][0], Q[ln][1], h, l);
            sQh[row0 * 52 + kp] = h; sQl[row0 * 52 + kp] = l;
            hl_split(Q[ln][2], Q[ln][3], h, l);
            sQh[(row0 + 8) * 52 + kp] = h; sQl[(row0 + 8) * 52 + kp] = l;
        }
    }
    __syncthreads();

    // -------- stage 2: O = P Ur^T + Q Ui^T (full k from smem) --------
    float O[7][4];
    #pragma unroll
    for (int n = 0; n < 7; ++n)
        #pragma unroll
        for (int r = 0; r < 4; ++r) O[n][r] = 0.f;

    const int mstrB = 2 * KT * NT * 32 * 2;
    const int sstrB = KT * NT * 32 * 2;
    const int row0  = wm * 16 + nl;
    const int row1  = row0 + 8;

    #pragma unroll
    for (int t = 0; t < KT; ++t) {
        const int kp0 = 8 * t + mm;
        const int kp1 = kp0 + 4;
        uint32_t PAH[4], PAL[4], QAH[4], QAL[4];
        PAH[0] = sPh[row0 * 52 + kp0]; PAH[1] = sPh[row1 * 52 + kp0];
        PAL[0] = sPl[row0 * 52 + kp0]; PAL[1] = sPl[row1 * 52 + kp0];
        QAH[0] = sQh[row0 * 52 + kp0]; QAH[1] = sQh[row1 * 52 + kp0];
        QAL[0] = sQl[row0 * 52 + kp0]; QAL[1] = sQl[row1 * 52 + kp0];
        if (kp1 < 52) {
            PAH[2] = sPh[row0 * 52 + kp1]; PAH[3] = sPh[row1 * 52 + kp1];
            PAL[2] = sPl[row0 * 52 + kp1]; PAL[3] = sPl[row1 * 52 + kp1];
            QAH[2] = sQh[row0 * 52 + kp1]; QAH[3] = sQh[row1 * 52 + kp1];
            QAL[2] = sQl[row0 * 52 + kp1]; QAL[3] = sQl[row1 * 52 + kp1];
        } else {
            PAH[2] = PAH[3] = PAL[2] = PAL[3] = 0u;
            QAH[2] = QAH[3] = QAL[2] = QAL[3] = 0u;
        }

        #pragma unroll
        for (int ln = 0; ln < 7; ++ln) {
            if (ln >= ncnt) break;
            const int n  = nbase + ln;
            const int bB = ((t * NT + n) * 32 + lane) * 2;
            uint2 brh = *(const uint2*)&g_B2[bB];
            uint2 brl = *(const uint2*)&g_B2[bB + sstrB];
            uint2 bih = *(const uint2*)&g_B2[bB + mstrB];
            uint2 bil = *(const uint2*)&g_B2[bB + mstrB + sstrB];
            mma16816(O[ln], PAH, brh.x, brh.y);
            mma16816(O[ln], PAH, brl.x, brl.y);
            mma16816(O[ln], PAL, brh.x, brh.y);
            mma16816(O[ln], QAH, bih.x, bih.y);
            mma16816(O[ln], QAH, bil.x, bil.y);
            mma16816(O[ln], QAL, bih.x, bih.y);
        }
    }

    // -------- store --------
    #pragma unroll
    for (int ln = 0; ln < 7; ++ln) {
        if (ln >= ncnt) break;
        const int n  = nbase + ln;
        const int c0 = n * 8 + 2 * mm;
        if (c0 + 1 >= DIM) continue;
        if (row0 < DIM) {
            const int idx = base + row0 * DIM + c0;
            if (idx + 2 <= out_floats)
                *(float2*)&outf[idx] = make_float2(O[ln][0], O[ln][1]);
        }
        if (row1 < DIM) {
            const int idx = base + row1 * DIM + c0;
            if (idx + 2 <= out_floats)
                *(float2*)&outf[idx] = make_float2(O[ln][2], O[ln][3]);
        }
    }
}

// Diagnostic fallback
__global__ void diag_mark_kernel(float* out) { out[0] = 0.0f; }

extern "C" void kernel_launch(void* const* d_in, const int* in_sizes, int n_in,
                              void* d_out, int out_size) {
    int smin = 0x7fffffff;
    for (int i = 0; i < n_in; ++i)
        if (in_sizes[i] < smin) smin = in_sizes[i];

    int unit = 0;
    if (smin == DIM)          unit = 1;
    else if (smin == DIM * 4) unit = 4;

    const float* xre = nullptr; const float* xim = nullptr;
    const float* theta = nullptr; const float* phi = nullptr;
    const float* diag = nullptr;
    int nbatch = 0, big = 0;
    bool ok = (unit != 0) && (n_in == 5);

    if (ok) {
        int norm[8];
        int diag_slot = -1;
        for (int i = 0; i < n_in; ++i) {
            norm[i] = in_sizes[i] / unit;
            if (norm[i] == DIM) diag_slot = i;
            if (norm[i] > big) big = norm[i];
        }
        if (diag_slot == 0 && norm[1] == KBS && norm[2] == KBS) {
            diag  = (const float*)d_in[0];
            phi   = (const float*)d_in[1];
            theta = (const float*)d_in[2];
            xre   = (const float*)d_in[3];
            xim   = (const float*)d_in[4];
        } else {
            for (int i = 0; i < n_in; ++i) {
                const float* p = (const float*)d_in[i];
                if (norm[i] == KBS)      { if (!theta) theta = p; else phi = p; }
                else if (norm[i] == DIM) { diag = p; }
                else if (norm[i] == big) { if (!xre) xre = p; else xim = p; }
            }
        }
        nbatch = big / NN;
        ok = xre && xim && theta && phi && diag &&
             nbatch > 0 && nbatch <= MAXB && (big == nbatch * NN);
    }

    if (!ok) {
        diag_mark_kernel<<<1, 1>>>((float*)d_out);
        return;
    }

    const int want = nbatch * NN;
    const int out_floats = (out_size < want) ? out_size : want;

    cudaFuncSetAttribute(fused_mma,
                         cudaFuncAttributeMaxDynamicSharedMemorySize, SMEM_DYN);

    rot_prep<<<(KBS + 127) / 128, 128>>>(theta, phi, diag);
    build_U<<<DIM, 64>>>();
    frag_prep<<<128, 256>>>();
    fused_mma<<<nbatch, 512, SMEM_DYN>>>(xre, xim, (float*)d_out, out_floats);
}